// round 9
// baseline (speedup 1.0000x reference)
#include <cuda_runtime.h>
#include <cuda_fp16.h>
#include <cstdint>

// GAT forward_user: mma.sync m16n8k16 fp16, single-copy I tile via ldmatrix,
// double-buffered I+adj, one __syncthreads + one named barrier per tile.
//   S = Q.I^T  (B-frags: ldmatrix non-trans, k = dims)
//   P = exp(mask(leaky2(S/sqrt(D))));  l += rowsum(P)   [exp(-9e15)=0]
//   O += P.I   (B-frags: ldmatrix.trans, k = items)
// split-2 over items; reduce kernel normalizes.

#define D_     128
#define NU_    10000
#define NI_    12000
#define BM_    64
#define NRB_   157
#define NRPAD_ (NRB_*BM_)
#define NSPL_  2
#define IPS_   6000
#define TILES_ 94
#define NT_    256
#define SCALE_ 0.08838834764831843f

__device__ float g_op[NSPL_][(size_t)NRPAD_*D_];
__device__ float g_lp[NSPL_][NRPAD_];

// ---- helpers ----
__device__ __forceinline__ uint32_t h2u(float a, float b){
    __half2 h = __floats2half2_rn(a, b);
    return *(uint32_t*)&h;
}
__device__ __forceinline__ void mma16(float* d, const uint32_t* a, const uint32_t* b){
    asm volatile("mma.sync.aligned.m16n8k16.row.col.f32.f16.f16.f32 "
        "{%0,%1,%2,%3}, {%4,%5,%6,%7}, {%8,%9}, {%0,%1,%2,%3};"
        : "+f"(d[0]), "+f"(d[1]), "+f"(d[2]), "+f"(d[3])
        : "r"(a[0]), "r"(a[1]), "r"(a[2]), "r"(a[3]), "r"(b[0]), "r"(b[1]));
}
__device__ __forceinline__ void ldsm4(uint32_t* r, uint32_t a){
    asm volatile("ldmatrix.sync.aligned.m8n8.x4.shared.b16 {%0,%1,%2,%3}, [%4];"
        : "=r"(r[0]), "=r"(r[1]), "=r"(r[2]), "=r"(r[3]) : "r"(a));
}
__device__ __forceinline__ void ldsm4t(uint32_t* r, uint32_t a){
    asm volatile("ldmatrix.sync.aligned.m8n8.x4.trans.shared.b16 {%0,%1,%2,%3}, [%4];"
        : "=r"(r[0]), "=r"(r[1]), "=r"(r[2]), "=r"(r[3]) : "r"(a));
}
__device__ __forceinline__ uint32_t smem_u32(const void* p){
    uint32_t a;
    asm("{ .reg .u64 t; cvta.to.shared.u64 t, %1; cvt.u32.u64 %0, t; }" : "=r"(a) : "l"(p));
    return a;
}
__device__ __forceinline__ void cpa8(uint32_t dst, const void* src){
    asm volatile("cp.async.ca.shared.global [%0], [%1], 8;" :: "r"(dst), "l"(src));
}
#define CP_COMMIT() asm volatile("cp.async.commit_group;" ::: "memory")
#define CP_WAIT1()  asm volatile("cp.async.wait_group 1;" ::: "memory")
#define BARW(id)    asm volatile("bar.sync %0, %1;" :: "r"(id), "r"(64) : "memory")

__device__ __forceinline__ int swz128(int r, int c){
    return (r<<7) | ((((c>>2) ^ (r&7)) << 2) | (c&3));
}

// smem byte offsets
#define B_SQ   0         // Q A-frag: [wm*8+ks][lane] uint4          16384
#define B_I0   16384     // I fp16 [64 items][16 gran x 16B] swz     16384
#define B_I1   32768     //   (double buffer)                        16384
#define B_SP   49152     // P A-frag: [wm*4+kso][lane] uint4          8192
#define B_ADJ  57344     // adj ints [2][64][66]                     33792
#define ADJ_I  4224      // ints per adj buffer
#define B_L    91136     // 128 floats
#define SMEM_B 91648

// store one item row's 4 dims (lane-local) as fp16 into I buffer
#define STORE_I(bufoff, j, v) do{ \
    *(uint2*)(smc + (bufoff) + (j)*256 + ((((lane>>1) ^ ((j)&7)))<<4) \
              + ((lane&1)<<3)) = make_uint2(h2u((v).x,(v).y), h2u((v).z,(v).w)); \
}while(0)

__global__ __launch_bounds__(NT_, 2)
void gat_main(const float* __restrict__ ufea, const float* __restrict__ inter,
              const int* __restrict__ adj, const float* __restrict__ W,
              const float* __restrict__ bias)
{
    extern __shared__ char smc[];
    int*   sA = (int*)(smc + B_ADJ);
    float* sL = (float*)(smc + B_L);
    const uint32_t smb  = smem_u32(smc);
    const uint32_t sA_b = smb + B_ADJ;

    const int tid  = threadIdx.x;
    const int lane = tid & 31, warp = tid >> 5;
    const int g    = lane >> 2, tig = lane & 3;
    const int wm   = warp >> 1, wn  = warp & 1;
    const int row0  = blockIdx.x * BM_;
    const int split = blockIdx.y;
    const int item0 = split * IPS_;

    // ====== prologue: Q = ufea @ W^T + b (fp32 exact) -> fp16 A-frags ======
    {
        float* pU = (float*)(smc + B_I0);       // 32KB staging (I0+I1)
        float* pW = (float*)(smc + B_ADJ);      // 16KB staging (adj area)
        #pragma unroll
        for (int it = 0; it < 8; ++it){
            int idx = it*NT_ + tid;
            int r = idx >> 5, c4 = idx & 31;
            int gr = min(row0 + r, NU_-1);
            float4 v = *(const float4*)(ufea + (size_t)gr*D_ + c4*4);
            *(float4*)(pU + swz128(r, c4*4)) = v;
        }
        const int tx = tid & 15, ty = tid >> 4;
        uint32_t* sQw = (uint32_t*)(smc + B_SQ);
        #pragma unroll 1
        for (int h = 0; h < 4; ++h){
            __syncthreads();
            #pragma unroll
            for (int it = 0; it < 4; ++it){
                int idx = it*NT_ + tid;
                int lr = idx >> 5, c4 = idx & 31;
                float4 w = *(const float4*)(W + (size_t)(h*32+lr)*D_ + c4*4);
                *(float4*)(pW + swz128(lr, c4*4)) = w;
            }
            __syncthreads();
            float acc[4][2] = {};
            #pragma unroll
            for (int k4 = 0; k4 < 32; ++k4){
                float4 wv[2];
                #pragma unroll
                for (int j = 0; j < 2; ++j)
                    wv[j] = *(const float4*)(pW + swz128(tx*2+j, k4*4));
                #pragma unroll
                for (int i = 0; i < 4; ++i){
                    float4 uv = *(const float4*)(pU + swz128(ty*4+i, k4*4));
                    #pragma unroll
                    for (int j = 0; j < 2; ++j){
                        acc[i][j] += uv.x*wv[j].x; acc[i][j] += uv.y*wv[j].y;
                        acc[i][j] += uv.z*wv[j].z; acc[i][j] += uv.w*wv[j].w;
                    }
                }
            }
            const int c = h*32 + tx*2;
            const int ks = c >> 4, dd = c & 15;
            const int regb = (dd < 8) ? 0 : 2;
            const int tq = (dd & 7) >> 1;
            #pragma unroll
            for (int i = 0; i < 4; ++i){
                int r = ty*4 + i;
                int wmq = r >> 4, rw = r & 15, gq = rw & 7, hi = rw >> 3;
                uint32_t pk = h2u(acc[i][0] + bias[c], acc[i][1] + bias[c+1]);
                sQw[(((wmq*8 + ks)*32) + gq*4 + tq)*4 + regb + hi] = pk;
            }
        }
        __syncthreads();
    }

    // ====== pipeline prologue: adj(0) cp.async, I(0) -> buf0 ======
    const int cc2 = lane * 2;
    {
        #pragma unroll
        for (int itc = 0; itc < 8; ++itc){
            int rowa = itc*8 + warp;
            int gr = min(row0 + rowa, NU_-1);
            int lcc = cc2;                       // tile 0 cols
            const int* src = adj + (size_t)gr*NI_ + item0 + ((lcc < IPS_) ? lcc : 0);
            cpa8(sA_b + (uint32_t)((rowa*66 + cc2)*4), src);
        }
        CP_COMMIT();
        #pragma unroll
        for (int p = 0; p < 4; ++p){
            int j0 = (p*8 + warp)*2;
            int gm0 = min(item0 + j0,     NI_-1);
            int gm1 = min(item0 + j0 + 1, NI_-1);
            float4 v0 = *(const float4*)(inter + (size_t)gm0*D_ + lane*4);
            float4 v1 = *(const float4*)(inter + (size_t)gm1*D_ + lane*4);
            STORE_I(B_I0, j0,   v0);
            STORE_I(B_I0, j0+1, v1);
        }
    }
    __syncthreads();

    // ====== mainloop ======
    float oacc[8][4];
    #pragma unroll
    for (int i = 0; i < 8; ++i)
        #pragma unroll
        for (int j = 0; j < 4; ++j) oacc[i][j] = 0.f;
    float lacc0 = 0.f, lacc1 = 0.f;

    const int m0 = wm*16, n0 = wn*32, nd0 = wn*64;
    const int laneM = lane & 7;
    // S ldmatrix row/chunk decomposition: m0,m1 = chunk+0/+1 ; m2,m3 = rows+8
    const int jloS = ((lane>>4)&1) << 3, chS = (lane>>3)&1;
    // O (trans): m0,m1 = rows+0/+8 ; m2,m3 = chunk+1
    const int jloO = ((lane>>3)&1) << 3, chO = (lane>>4)&1;
    const int jS0 = n0 + jloS + laneM,  jS1 = jS0 + 16;
    const uint32_t rbS0 = (uint32_t)(jS0*256), rbS1 = (uint32_t)(jS1*256);
    const int j7S0 = jS0 & 7, j7S1 = jS1 & 7;

    #pragma unroll 1
    for (int t = 0; t < TILES_; ++t){
        const int cur = t & 1, nxt = cur ^ 1;
        const uint32_t ibase = smb + (cur ? B_I1 : B_I0);

        // ---- adj(t+1) cp.async into other buffer ----
        if (t+1 < TILES_){
            const int tcol = (t+1)*64;
            #pragma unroll
            for (int itc = 0; itc < 8; ++itc){
                int rowa = itc*8 + warp;
                int gr = min(row0 + rowa, NU_-1);
                int lcc = tcol + cc2;
                const int* src = adj + (size_t)gr*NI_ + item0 + ((lcc < IPS_) ? lcc : 0);
                cpa8(sA_b + (uint32_t)((nxt*ADJ_I + rowa*66 + cc2)*4), src);
            }
        }
        CP_COMMIT();

        // ---- I(t+1) gmem prefetch (first half) ----
        float4 pv0[4];
        if (t+1 < TILES_){
            #pragma unroll
            for (int p = 0; p < 2; ++p){
                int j0 = (p*8 + warp)*2;
                int gm0 = min(item0 + (t+1)*64 + j0,     NI_-1);
                int gm1 = min(item0 + (t+1)*64 + j0 + 1, NI_-1);
                pv0[p*2]   = *(const float4*)(inter + (size_t)gm0*D_ + lane*4);
                pv0[p*2+1] = *(const float4*)(inter + (size_t)gm1*D_ + lane*4);
            }
        }

        // ---- S = Q . I^T  (16 rows x 32 items per warp) ----
        float sacc[4][4];
        #pragma unroll
        for (int nf = 0; nf < 4; ++nf)
            #pragma unroll
            for (int j = 0; j < 4; ++j) sacc[nf][j] = 0.f;
        #pragma unroll
        for (int ks = 0; ks < 8; ++ks){
            uint4 a4 = *(const uint4*)(smc + B_SQ + (((wm*8+ks)*32 + lane)<<4));
            const uint32_t A[4] = { a4.x, a4.y, a4.z, a4.w };
            uint32_t r[4];
            ldsm4(r, ibase + rbS0 + (uint32_t)((((2*ks + chS) ^ j7S0))<<4));
            mma16(sacc[0], A, r);
            mma16(sacc[1], A, r+2);
            ldsm4(r, ibase + rbS1 + (uint32_t)((((2*ks + chS) ^ j7S1))<<4));
            mma16(sacc[2], A, r);
            mma16(sacc[3], A, r+2);
        }

        // ---- I(t+1) gmem prefetch (second half) ----
        float4 pv1[4];
        if (t+1 < TILES_){
            #pragma unroll
            for (int p = 2; p < 4; ++p){
                int j0 = (p*8 + warp)*2;
                int gm0 = min(item0 + (t+1)*64 + j0,     NI_-1);
                int gm1 = min(item0 + (t+1)*64 + j0 + 1, NI_-1);
                pv1[(p-2)*2]   = *(const float4*)(inter + (size_t)gm0*D_ + lane*4);
                pv1[(p-2)*2+1] = *(const float4*)(inter + (size_t)gm1*D_ + lane*4);
            }
        }

        CP_WAIT1();                              // adj(t) landed

        // ---- epilogue: scale, leaky2, mask, exp; P -> fp16 A-frags ----
        const int* sAc = sA + cur*ADJ_I;
        #pragma unroll
        for (int nf = 0; nf < 4; ++nf){
            const int c0 = n0 + nf*8 + 2*tig;
            const int lc = t*64 + c0;
            int2 a0 = make_int2(0,0), a1 = make_int2(0,0);
            if (lc < IPS_){
                a0 = *(const int2*)(sAc + (m0+g)*66 + c0);
                a1 = *(const int2*)(sAc + (m0+8+g)*66 + c0);
            }
            float v00 = sacc[nf][0]*SCALE_; v00 = fminf(v00, 2.f*v00);
            float v01 = sacc[nf][1]*SCALE_; v01 = fminf(v01, 2.f*v01);
            float v10 = sacc[nf][2]*SCALE_; v10 = fminf(v10, 2.f*v10);
            float v11 = sacc[nf][3]*SCALE_; v11 = fminf(v11, 2.f*v11);
            float p00 = (a0.x > 0) ? __expf(v00) : 0.f;
            float p01 = (a0.y > 0) ? __expf(v01) : 0.f;
            float p10 = (a1.x > 0) ? __expf(v10) : 0.f;
            float p11 = (a1.y > 0) ? __expf(v11) : 0.f;
            lacc0 += p00 + p01;
            lacc1 += p10 + p11;
            sacc[nf][0] = p00; sacc[nf][1] = p01;
            sacc[nf][2] = p10; sacc[nf][3] = p11;
        }
        #pragma unroll
        for (int kl = 0; kl < 2; ++kl){
            uint4 pk;
            pk.x = h2u(sacc[2*kl][0],   sacc[2*kl][1]);
            pk.y = h2u(sacc[2*kl][2],   sacc[2*kl][3]);
            pk.z = h2u(sacc[2*kl+1][0], sacc[2*kl+1][1]);
            pk.w = h2u(sacc[2*kl+1][2], sacc[2*kl+1][3]);
            *(uint4*)(smc + B_SP + (((wm*4 + wn*2 + kl)*32 + lane)<<4)) = pk;
        }
        BARW(1 + wm);                            // P visible within wm-pair

        // ---- O += P . I  (16 rows x 64 dims per warp) ----
        #pragma unroll
        for (int kso = 0; kso < 4; ++kso){
            uint4 a4 = *(const uint4*)(smc + B_SP + (((wm*4+kso)*32 + lane)<<4));
            const uint32_t A[4] = { a4.x, a4.y, a4.z, a4.w };
            const int j = kso*16 + jloO + laneM;
            const uint32_t rb = ibase + (uint32_t)(j*256);
            const int j7 = j & 7;
            #pragma unroll
            for (int nh = 0; nh < 4; ++nh){
                uint32_t r[4];
                ldsm4t(r, rb + (uint32_t)(((((nd0>>3) + nh*2 + chO) ^ j7))<<4));
                mma16(oacc[nh*2],   A, r);
                mma16(oacc[nh*2+1], A, r+2);
            }
        }

        // ---- store I(t+1) into other buffer ----
        if (t+1 < TILES_){
            const int joff0 = warp*2, joff1 = 16 + warp*2,
                      joff2 = 32 + warp*2, joff3 = 48 + warp*2;
            STORE_I((nxt? B_I1 : B_I0), joff0,   pv0[0]);
            STORE_I((nxt? B_I1 : B_I0), joff0+1, pv0[1]);
            STORE_I((nxt? B_I1 : B_I0), joff1,   pv0[2]);
            STORE_I((nxt? B_I1 : B_I0), joff1+1, pv0[3]);
            STORE_I((nxt? B_I1 : B_I0), joff2,   pv1[0]);
            STORE_I((nxt? B_I1 : B_I0), joff2+1, pv1[1]);
            STORE_I((nxt? B_I1 : B_I0), joff3,   pv1[2]);
            STORE_I((nxt? B_I1 : B_I0), joff3+1, pv1[3]);
        }
        __syncthreads();                         // publish buffers
    }

    // ---- l reduction ----
    lacc0 += __shfl_xor_sync(0xffffffffu, lacc0, 1);
    lacc0 += __shfl_xor_sync(0xffffffffu, lacc0, 2);
    lacc1 += __shfl_xor_sync(0xffffffffu, lacc1, 1);
    lacc1 += __shfl_xor_sync(0xffffffffu, lacc1, 2);
    if (tig == 0){
        sL[wn*64 + m0 + g]     = lacc0;
        sL[wn*64 + m0 + 8 + g] = lacc1;
    }
    __syncthreads();
    if (tid < BM_) g_lp[split][row0 + tid] = sL[tid] + sL[64 + tid];

    // ---- write unnormalized partial O ----
    {
        const int r0g = row0 + m0 + g, r1g = row0 + m0 + 8 + g;
        #pragma unroll
        for (int nf = 0; nf < 8; ++nf){
            const int dd = nd0 + nf*8 + 2*tig;
            if (r0g < NU_)
                *(float2*)(&g_op[split][(size_t)r0g*D_ + dd]) =
                    make_float2(oacc[nf][0], oacc[nf][1]);
            if (r1g < NU_)
                *(float2*)(&g_op[split][(size_t)r1g*D_ + dd]) =
                    make_float2(oacc[nf][2], oacc[nf][3]);
        }
    }
}

// ================= combine splits & normalize =================
__global__ __launch_bounds__(256) void gat_reduce(float* __restrict__ out)
{
    int idx = blockIdx.x*256 + threadIdx.x;
    int rr = idx >> 5, c4 = idx & 31;
    if (rr >= NU_) return;
    float l = g_lp[0][rr] + g_lp[1][rr];
    float4 a = *(const float4*)(&g_op[0][(size_t)rr*D_ + c4*4]);
    float4 b = *(const float4*)(&g_op[1][(size_t)rr*D_ + c4*4]);
    float inv = 1.0f / l;
    float4 o = make_float4((a.x+b.x)*inv, (a.y+b.y)*inv,
                           (a.z+b.z)*inv, (a.w+b.w)*inv);
    *(float4*)(out + (size_t)rr*D_ + c4*4) = o;
}

extern "C" void kernel_launch(void* const* d_in, const int* in_sizes, int n_in,
                              void* d_out, int out_size)
{
    const float* ufea  = (const float*)d_in[0];
    const float* inter = (const float*)d_in[1];
    const int*   adj   = (const int*)  d_in[2];
    const float* W     = (const float*)d_in[3];
    const float* bias  = (const float*)d_in[4];
    for (int i = 0; i < n_in; ++i) {
        int s = in_sizes[i];
        if      (s == NU_*D_)  ufea  = (const float*)d_in[i];
        else if (s == NI_*D_)  inter = (const float*)d_in[i];
        else if (s == NU_*NI_) adj   = (const int*)d_in[i];
        else if (s == D_*D_)   W     = (const float*)d_in[i];
        else if (s == D_)      bias  = (const float*)d_in[i];
    }

    cudaFuncSetAttribute(gat_main, cudaFuncAttributeMaxDynamicSharedMemorySize,
                         SMEM_B);

    dim3 grid(NRB_, NSPL_);                      // 157 x 2 = 314 CTAs
    gat_main<<<grid, NT_, SMEM_B>>>(ufea, inter, adj, W, bias);
    gat_reduce<<<(NU_*32 + 255)/256, 256>>>((float*)d_out);
}

// round 10
// speedup vs baseline: 1.0015x; 1.0015x over previous
#include <cuda_runtime.h>
#include <cuda_fp16.h>
#include <cstdint>

// GAT forward_user: mma.sync m16n8k16 fp16, single-copy I tile via ldmatrix,
// double-buffered I+adj, one __syncthreads + one named barrier per tile.
//   S = Q.I^T  (B-frags: ldmatrix non-trans, k = dims)
//   P = exp(mask(leaky2(S/sqrt(D))));  l += rowsum(P)   [exp(-9e15)=0]
//   O += P.I   (B-frags: ldmatrix.trans, k = items)
// split-2 over items; reduce kernel normalizes.

#define D_     128
#define NU_    10000
#define NI_    12000
#define BM_    64
#define NRB_   157
#define NRPAD_ (NRB_*BM_)
#define NSPL_  2
#define IPS_   6000
#define TILES_ 94
#define NT_    256
#define SCALE_ 0.08838834764831843f

__device__ float g_op[NSPL_][(size_t)NRPAD_*D_];
__device__ float g_lp[NSPL_][NRPAD_];

// ---- helpers ----
__device__ __forceinline__ uint32_t h2u(float a, float b){
    __half2 h = __floats2half2_rn(a, b);
    return *(uint32_t*)&h;
}
__device__ __forceinline__ void mma16(float* d, const uint32_t* a, const uint32_t* b){
    asm volatile("mma.sync.aligned.m16n8k16.row.col.f32.f16.f16.f32 "
        "{%0,%1,%2,%3}, {%4,%5,%6,%7}, {%8,%9}, {%0,%1,%2,%3};"
        : "+f"(d[0]), "+f"(d[1]), "+f"(d[2]), "+f"(d[3])
        : "r"(a[0]), "r"(a[1]), "r"(a[2]), "r"(a[3]), "r"(b[0]), "r"(b[1]));
}
__device__ __forceinline__ void ldsm4(uint32_t* r, uint32_t a){
    asm volatile("ldmatrix.sync.aligned.m8n8.x4.shared.b16 {%0,%1,%2,%3}, [%4];"
        : "=r"(r[0]), "=r"(r[1]), "=r"(r[2]), "=r"(r[3]) : "r"(a));
}
__device__ __forceinline__ void ldsm4t(uint32_t* r, uint32_t a){
    asm volatile("ldmatrix.sync.aligned.m8n8.x4.trans.shared.b16 {%0,%1,%2,%3}, [%4];"
        : "=r"(r[0]), "=r"(r[1]), "=r"(r[2]), "=r"(r[3]) : "r"(a));
}
__device__ __forceinline__ uint32_t smem_u32(const void* p){
    uint32_t a;
    asm("{ .reg .u64 t; cvta.to.shared.u64 t, %1; cvt.u32.u64 %0, t; }" : "=r"(a) : "l"(p));
    return a;
}
__device__ __forceinline__ void cpa8(uint32_t dst, const void* src){
    asm volatile("cp.async.ca.shared.global [%0], [%1], 8;" :: "r"(dst), "l"(src));
}
#define CP_COMMIT() asm volatile("cp.async.commit_group;" ::: "memory")
#define CP_WAIT1()  asm volatile("cp.async.wait_group 1;" ::: "memory")
#define BARW(id)    asm volatile("bar.sync %0, %1;" :: "r"(id), "r"(64) : "memory")

__device__ __forceinline__ int swz128(int r, int c){
    return (r<<7) | ((((c>>2) ^ (r&7)) << 2) | (c&3));
}

// smem byte offsets
#define B_SQ   0         // Q A-frag: [wm*8+ks][lane] uint4          16384
#define B_I0   16384     // I fp16 [64 items][16 gran x 16B] swz     16384
#define B_I1   32768     //   (double buffer)                        16384
#define B_SP   49152     // P A-frag: [wm*4+kso][lane] uint4          8192
#define B_ADJ  57344     // adj ints [2][64][66]                     33792
#define ADJ_I  4224      // ints per adj buffer
#define B_L    91136     // 128 floats
#define SMEM_B 91648

// store one item row's 4 dims (lane-local) as fp16 into I buffer
#define STORE_I(bufoff, j, v) do{ \
    *(uint2*)(smc + (bufoff) + (j)*256 + ((((lane>>1) ^ ((j)&7)))<<4) \
              + ((lane&1)<<3)) = make_uint2(h2u((v).x,(v).y), h2u((v).z,(v).w)); \
}while(0)

__global__ __launch_bounds__(NT_, 2)
void gat_main(const float* __restrict__ ufea, const float* __restrict__ inter,
              const int* __restrict__ adj, const float* __restrict__ W,
              const float* __restrict__ bias)
{
    extern __shared__ char smc[];
    int*   sA = (int*)(smc + B_ADJ);
    float* sL = (float*)(smc + B_L);
    const uint32_t smb  = smem_u32(smc);
    const uint32_t sA_b = smb + B_ADJ;

    const int tid  = threadIdx.x;
    const int lane = tid & 31, warp = tid >> 5;
    const int g    = lane >> 2, tig = lane & 3;
    const int wm   = warp >> 1, wn  = warp & 1;
    const int row0  = blockIdx.x * BM_;
    const int split = blockIdx.y;
    const int item0 = split * IPS_;

    // ====== prologue: Q = ufea @ W^T + b (fp32 exact) -> fp16 A-frags ======
    {
        float* pU = (float*)(smc + B_I0);       // 32KB staging (I0+I1)
        float* pW = (float*)(smc + B_ADJ);      // 16KB staging (adj area)
        #pragma unroll
        for (int it = 0; it < 8; ++it){
            int idx = it*NT_ + tid;
            int r = idx >> 5, c4 = idx & 31;
            int gr = min(row0 + r, NU_-1);
            float4 v = *(const float4*)(ufea + (size_t)gr*D_ + c4*4);
            *(float4*)(pU + swz128(r, c4*4)) = v;
        }
        const int tx = tid & 15, ty = tid >> 4;
        uint32_t* sQw = (uint32_t*)(smc + B_SQ);
        #pragma unroll 1
        for (int h = 0; h < 4; ++h){
            __syncthreads();
            #pragma unroll
            for (int it = 0; it < 4; ++it){
                int idx = it*NT_ + tid;
                int lr = idx >> 5, c4 = idx & 31;
                float4 w = *(const float4*)(W + (size_t)(h*32+lr)*D_ + c4*4);
                *(float4*)(pW + swz128(lr, c4*4)) = w;
            }
            __syncthreads();
            float acc[4][2] = {};
            #pragma unroll
            for (int k4 = 0; k4 < 32; ++k4){
                float4 wv[2];
                #pragma unroll
                for (int j = 0; j < 2; ++j)
                    wv[j] = *(const float4*)(pW + swz128(tx*2+j, k4*4));
                #pragma unroll
                for (int i = 0; i < 4; ++i){
                    float4 uv = *(const float4*)(pU + swz128(ty*4+i, k4*4));
                    #pragma unroll
                    for (int j = 0; j < 2; ++j){
                        acc[i][j] += uv.x*wv[j].x; acc[i][j] += uv.y*wv[j].y;
                        acc[i][j] += uv.z*wv[j].z; acc[i][j] += uv.w*wv[j].w;
                    }
                }
            }
            const int c = h*32 + tx*2;
            const int ks = c >> 4, dd = c & 15;
            const int regb = (dd < 8) ? 0 : 2;
            const int tq = (dd & 7) >> 1;
            #pragma unroll
            for (int i = 0; i < 4; ++i){
                int r = ty*4 + i;
                int wmq = r >> 4, rw = r & 15, gq = rw & 7, hi = rw >> 3;
                uint32_t pk = h2u(acc[i][0] + bias[c], acc[i][1] + bias[c+1]);
                sQw[(((wmq*8 + ks)*32) + gq*4 + tq)*4 + regb + hi] = pk;
            }
        }
        __syncthreads();
    }

    // ====== pipeline prologue: adj(0) cp.async, I(0) -> buf0 ======
    const int cc2 = lane * 2;
    {
        #pragma unroll
        for (int itc = 0; itc < 8; ++itc){
            int rowa = itc*8 + warp;
            int gr = min(row0 + rowa, NU_-1);
            int lcc = cc2;                       // tile 0 cols
            const int* src = adj + (size_t)gr*NI_ + item0 + ((lcc < IPS_) ? lcc : 0);
            cpa8(sA_b + (uint32_t)((rowa*66 + cc2)*4), src);
        }
        CP_COMMIT();
        #pragma unroll
        for (int p = 0; p < 4; ++p){
            int j0 = (p*8 + warp)*2;
            int gm0 = min(item0 + j0,     NI_-1);
            int gm1 = min(item0 + j0 + 1, NI_-1);
            float4 v0 = *(const float4*)(inter + (size_t)gm0*D_ + lane*4);
            float4 v1 = *(const float4*)(inter + (size_t)gm1*D_ + lane*4);
            STORE_I(B_I0, j0,   v0);
            STORE_I(B_I0, j0+1, v1);
        }
    }
    __syncthreads();

    // ====== mainloop ======
    float oacc[8][4];
    #pragma unroll
    for (int i = 0; i < 8; ++i)
        #pragma unroll
        for (int j = 0; j < 4; ++j) oacc[i][j] = 0.f;
    float lacc0 = 0.f, lacc1 = 0.f;

    const int m0 = wm*16, n0 = wn*32, nd0 = wn*64;
    const int laneM = lane & 7;
    // S ldmatrix row/chunk decomposition: m0,m1 = chunk+0/+1 ; m2,m3 = rows+8
    const int jloS = ((lane>>4)&1) << 3, chS = (lane>>3)&1;
    // O (trans): m0,m1 = rows+0/+8 ; m2,m3 = chunk+1
    const int jloO = ((lane>>3)&1) << 3, chO = (lane>>4)&1;
    const int jS0 = n0 + jloS + laneM,  jS1 = jS0 + 16;
    const uint32_t rbS0 = (uint32_t)(jS0*256), rbS1 = (uint32_t)(jS1*256);
    const int j7S0 = jS0 & 7, j7S1 = jS1 & 7;

    #pragma unroll 1
    for (int t = 0; t < TILES_; ++t){
        const int cur = t & 1, nxt = cur ^ 1;
        const uint32_t ibase = smb + (cur ? B_I1 : B_I0);

        // ---- adj(t+1) cp.async into other buffer ----
        if (t+1 < TILES_){
            const int tcol = (t+1)*64;
            #pragma unroll
            for (int itc = 0; itc < 8; ++itc){
                int rowa = itc*8 + warp;
                int gr = min(row0 + rowa, NU_-1);
                int lcc = tcol + cc2;
                const int* src = adj + (size_t)gr*NI_ + item0 + ((lcc < IPS_) ? lcc : 0);
                cpa8(sA_b + (uint32_t)((nxt*ADJ_I + rowa*66 + cc2)*4), src);
            }
        }
        CP_COMMIT();

        // ---- I(t+1) gmem prefetch (first half) ----
        float4 pv0[4];
        if (t+1 < TILES_){
            #pragma unroll
            for (int p = 0; p < 2; ++p){
                int j0 = (p*8 + warp)*2;
                int gm0 = min(item0 + (t+1)*64 + j0,     NI_-1);
                int gm1 = min(item0 + (t+1)*64 + j0 + 1, NI_-1);
                pv0[p*2]   = *(const float4*)(inter + (size_t)gm0*D_ + lane*4);
                pv0[p*2+1] = *(const float4*)(inter + (size_t)gm1*D_ + lane*4);
            }
        }

        // ---- S = Q . I^T  (16 rows x 32 items per warp) ----
        float sacc[4][4];
        #pragma unroll
        for (int nf = 0; nf < 4; ++nf)
            #pragma unroll
            for (int j = 0; j < 4; ++j) sacc[nf][j] = 0.f;
        #pragma unroll
        for (int ks = 0; ks < 8; ++ks){
            uint4 a4 = *(const uint4*)(smc + B_SQ + (((wm*8+ks)*32 + lane)<<4));
            const uint32_t A[4] = { a4.x, a4.y, a4.z, a4.w };
            uint32_t r[4];
            ldsm4(r, ibase + rbS0 + (uint32_t)((((2*ks + chS) ^ j7S0))<<4));
            mma16(sacc[0], A, r);
            mma16(sacc[1], A, r+2);
            ldsm4(r, ibase + rbS1 + (uint32_t)((((2*ks + chS) ^ j7S1))<<4));
            mma16(sacc[2], A, r);
            mma16(sacc[3], A, r+2);
        }

        // ---- I(t+1) gmem prefetch (second half) ----
        float4 pv1[4];
        if (t+1 < TILES_){
            #pragma unroll
            for (int p = 2; p < 4; ++p){
                int j0 = (p*8 + warp)*2;
                int gm0 = min(item0 + (t+1)*64 + j0,     NI_-1);
                int gm1 = min(item0 + (t+1)*64 + j0 + 1, NI_-1);
                pv1[(p-2)*2]   = *(const float4*)(inter + (size_t)gm0*D_ + lane*4);
                pv1[(p-2)*2+1] = *(const float4*)(inter + (size_t)gm1*D_ + lane*4);
            }
        }

        CP_WAIT1();                              // adj(t) landed

        // ---- epilogue: scale, leaky2, mask, exp; P -> fp16 A-frags ----
        const int* sAc = sA + cur*ADJ_I;
        #pragma unroll
        for (int nf = 0; nf < 4; ++nf){
            const int c0 = n0 + nf*8 + 2*tig;
            const int lc = t*64 + c0;
            int2 a0 = make_int2(0,0), a1 = make_int2(0,0);
            if (lc < IPS_){
                a0 = *(const int2*)(sAc + (m0+g)*66 + c0);
                a1 = *(const int2*)(sAc + (m0+8+g)*66 + c0);
            }
            float v00 = sacc[nf][0]*SCALE_; v00 = fminf(v00, 2.f*v00);
            float v01 = sacc[nf][1]*SCALE_; v01 = fminf(v01, 2.f*v01);
            float v10 = sacc[nf][2]*SCALE_; v10 = fminf(v10, 2.f*v10);
            float v11 = sacc[nf][3]*SCALE_; v11 = fminf(v11, 2.f*v11);
            float p00 = (a0.x > 0) ? __expf(v00) : 0.f;
            float p01 = (a0.y > 0) ? __expf(v01) : 0.f;
            float p10 = (a1.x > 0) ? __expf(v10) : 0.f;
            float p11 = (a1.y > 0) ? __expf(v11) : 0.f;
            lacc0 += p00 + p01;
            lacc1 += p10 + p11;
            sacc[nf][0] = p00; sacc[nf][1] = p01;
            sacc[nf][2] = p10; sacc[nf][3] = p11;
        }
        #pragma unroll
        for (int kl = 0; kl < 2; ++kl){
            uint4 pk;
            pk.x = h2u(sacc[2*kl][0],   sacc[2*kl][1]);
            pk.y = h2u(sacc[2*kl][2],   sacc[2*kl][3]);
            pk.z = h2u(sacc[2*kl+1][0], sacc[2*kl+1][1]);
            pk.w = h2u(sacc[2*kl+1][2], sacc[2*kl+1][3]);
            *(uint4*)(smc + B_SP + (((wm*4 + wn*2 + kl)*32 + lane)<<4)) = pk;
        }
        BARW(1 + wm);                            // P visible within wm-pair

        // ---- O += P . I  (16 rows x 64 dims per warp) ----
        #pragma unroll
        for (int kso = 0; kso < 4; ++kso){
            uint4 a4 = *(const uint4*)(smc + B_SP + (((wm*4+kso)*32 + lane)<<4));
            const uint32_t A[4] = { a4.x, a4.y, a4.z, a4.w };
            const int j = kso*16 + jloO + laneM;
            const uint32_t rb = ibase + (uint32_t)(j*256);
            const int j7 = j & 7;
            #pragma unroll
            for (int nh = 0; nh < 4; ++nh){
                uint32_t r[4];
                ldsm4t(r, rb + (uint32_t)(((((nd0>>3) + nh*2 + chO) ^ j7))<<4));
                mma16(oacc[nh*2],   A, r);
                mma16(oacc[nh*2+1], A, r+2);
            }
        }

        // ---- store I(t+1) into other buffer ----
        if (t+1 < TILES_){
            const int joff0 = warp*2, joff1 = 16 + warp*2,
                      joff2 = 32 + warp*2, joff3 = 48 + warp*2;
            STORE_I((nxt? B_I1 : B_I0), joff0,   pv0[0]);
            STORE_I((nxt? B_I1 : B_I0), joff0+1, pv0[1]);
            STORE_I((nxt? B_I1 : B_I0), joff1,   pv0[2]);
            STORE_I((nxt? B_I1 : B_I0), joff1+1, pv0[3]);
            STORE_I((nxt? B_I1 : B_I0), joff2,   pv1[0]);
            STORE_I((nxt? B_I1 : B_I0), joff2+1, pv1[1]);
            STORE_I((nxt? B_I1 : B_I0), joff3,   pv1[2]);
            STORE_I((nxt? B_I1 : B_I0), joff3+1, pv1[3]);
        }
        __syncthreads();                         // publish buffers
    }

    // ---- l reduction ----
    lacc0 += __shfl_xor_sync(0xffffffffu, lacc0, 1);
    lacc0 += __shfl_xor_sync(0xffffffffu, lacc0, 2);
    lacc1 += __shfl_xor_sync(0xffffffffu, lacc1, 1);
    lacc1 += __shfl_xor_sync(0xffffffffu, lacc1, 2);
    if (tig == 0){
        sL[wn*64 + m0 + g]     = lacc0;
        sL[wn*64 + m0 + 8 + g] = lacc1;
    }
    __syncthreads();
    if (tid < BM_) g_lp[split][row0 + tid] = sL[tid] + sL[64 + tid];

    // ---- write unnormalized partial O ----
    {
        const int r0g = row0 + m0 + g, r1g = row0 + m0 + 8 + g;
        #pragma unroll
        for (int nf = 0; nf < 8; ++nf){
            const int dd = nd0 + nf*8 + 2*tig;
            if (r0g < NU_)
                *(float2*)(&g_op[split][(size_t)r0g*D_ + dd]) =
                    make_float2(oacc[nf][0], oacc[nf][1]);
            if (r1g < NU_)
                *(float2*)(&g_op[split][(size_t)r1g*D_ + dd]) =
                    make_float2(oacc[nf][2], oacc[nf][3]);
        }
    }
}

// ================= combine splits & normalize =================
__global__ __launch_bounds__(256) void gat_reduce(float* __restrict__ out)
{
    int idx = blockIdx.x*256 + threadIdx.x;
    int rr = idx >> 5, c4 = idx & 31;
    if (rr >= NU_) return;
    float l = g_lp[0][rr] + g_lp[1][rr];
    float4 a = *(const float4*)(&g_op[0][(size_t)rr*D_ + c4*4]);
    float4 b = *(const float4*)(&g_op[1][(size_t)rr*D_ + c4*4]);
    float inv = 1.0f / l;
    float4 o = make_float4((a.x+b.x)*inv, (a.y+b.y)*inv,
                           (a.z+b.z)*inv, (a.w+b.w)*inv);
    *(float4*)(out + (size_t)rr*D_ + c4*4) = o;
}

extern "C" void kernel_launch(void* const* d_in, const int* in_sizes, int n_in,
                              void* d_out, int out_size)
{
    const float* ufea  = (const float*)d_in[0];
    const float* inter = (const float*)d_in[1];
    const int*   adj   = (const int*)  d_in[2];
    const float* W     = (const float*)d_in[3];
    const float* bias  = (const float*)d_in[4];
    for (int i = 0; i < n_in; ++i) {
        int s = in_sizes[i];
        if      (s == NU_*D_)  ufea  = (const float*)d_in[i];
        else if (s == NI_*D_)  inter = (const float*)d_in[i];
        else if (s == NU_*NI_) adj   = (const int*)d_in[i];
        else if (s == D_*D_)   W     = (const float*)d_in[i];
        else if (s == D_)      bias  = (const float*)d_in[i];
    }

    cudaFuncSetAttribute(gat_main, cudaFuncAttributeMaxDynamicSharedMemorySize,
                         SMEM_B);

    dim3 grid(NRB_, NSPL_);                      // 157 x 2 = 314 CTAs
    gat_main<<<grid, NT_, SMEM_B>>>(ufea, inter, adj, W, bias);
    gat_reduce<<<(NU_*32 + 255)/256, 256>>>((float*)d_out);
}

// round 12
// speedup vs baseline: 1.1294x; 1.1277x over previous
#include <cuda_runtime.h>
#include <cuda_fp16.h>
#include <cstdint>

// GAT forward_user: fp16 mma.sync + persistent CTAs with dynamic work queue.
//   gat_qk:   Q = ufea@W^T+b (fp32 exact) -> fp16 A-fragments in gmem
//   gat_main: 296 persistent CTAs pull units (row-block 64 x item-split of 8);
//             per 64-item tile: S=Q.I^T; P=exp(mask(leaky2(S/sqrt(D))));
//             l+=rowsum; O+=P.I ; partials to gmem.  exp(-9e15)=0 => no max.
//   gat_reduce: out = (sum_s O_s)/(sum_s l_s)

#define D_     128
#define NU_    10000
#define NI_    12000
#define BM_    64
#define NRB_   157
#define NRPAD_ (NRB_*BM_)
#define NSPL_  8
#define IPS_   1500
#define TILES_ 24            // 24*64 = 1536 >= 1500
#define UNITS_ (NRB_*NSPL_)  // 1256
#define GRID_  296
#define NT_    256
#define SCALE_ 0.08838834764831843f

__device__ float    g_op[NSPL_][(size_t)NRPAD_*D_];
__device__ float    g_lp[NSPL_][NRPAD_];
__device__ uint32_t g_qf[NRB_*4096];     // Q A-frags, 16KB per row-block
__device__ int      g_unit;

// ---- helpers ----
__device__ __forceinline__ uint32_t h2u(float a, float b){
    __half2 h = __floats2half2_rn(a, b);
    return *(uint32_t*)&h;
}
__device__ __forceinline__ void mma16(float* d, const uint32_t* a, const uint32_t* b){
    asm volatile("mma.sync.aligned.m16n8k16.row.col.f32.f16.f16.f32 "
        "{%0,%1,%2,%3}, {%4,%5,%6,%7}, {%8,%9}, {%0,%1,%2,%3};"
        : "+f"(d[0]), "+f"(d[1]), "+f"(d[2]), "+f"(d[3])
        : "r"(a[0]), "r"(a[1]), "r"(a[2]), "r"(a[3]), "r"(b[0]), "r"(b[1]));
}
__device__ __forceinline__ void ldsm4(uint32_t* r, uint32_t a){
    asm volatile("ldmatrix.sync.aligned.m8n8.x4.shared.b16 {%0,%1,%2,%3}, [%4];"
        : "=r"(r[0]), "=r"(r[1]), "=r"(r[2]), "=r"(r[3]) : "r"(a));
}
__device__ __forceinline__ void ldsm4t(uint32_t* r, uint32_t a){
    asm volatile("ldmatrix.sync.aligned.m8n8.x4.trans.shared.b16 {%0,%1,%2,%3}, [%4];"
        : "=r"(r[0]), "=r"(r[1]), "=r"(r[2]), "=r"(r[3]) : "r"(a));
}
__device__ __forceinline__ uint32_t smem_u32(const void* p){
    uint32_t a;
    asm("{ .reg .u64 t; cvta.to.shared.u64 t, %1; cvt.u32.u64 %0, t; }" : "=r"(a) : "l"(p));
    return a;
}
#define BARW(id) asm volatile("bar.sync %0, %1;" :: "r"(id), "r"(64) : "memory")

__device__ __forceinline__ int swz128(int r, int c){
    return (r<<7) | ((((c>>2) ^ (r&7)) << 2) | (c&3));
}

// smem byte offsets (gat_main)
#define B_SQ   0         // Q A-frag: [wm*8+ks][lane] uint4   16384
#define B_I0   16384     // I fp16 tile (double buffer)       16384
#define B_I1   32768     //                                   16384
#define B_SP   49152     // P A-frag                           8192
#define B_L    57344     // 128 floats                          512
#define B_U    57856     // unit broadcast                       16
#define SMEM_B 57984

#define STORE_I(bufoff, j, v) do{ \
    *(uint2*)(smc + (bufoff) + (j)*256 + ((((lane>>1) ^ ((j)&7)))<<4) \
              + ((lane&1)<<3)) = make_uint2(h2u((v).x,(v).y), h2u((v).z,(v).w)); \
}while(0)

// ================= init: reset work counter =================
__global__ void gat_init(){ g_unit = 0; }

// ================= Q kernel: fp32-exact, store fp16 A-frags =================
__global__ __launch_bounds__(NT_, 1)
void gat_qk(const float* __restrict__ ufea, const float* __restrict__ W,
            const float* __restrict__ bias)
{
    extern __shared__ char smc[];
    float* pU = (float*)smc;                 // 32KB
    float* pW = (float*)(smc + 32768);       // 16KB
    const int tid = threadIdx.x;
    const int row0 = blockIdx.x * BM_;
    uint32_t* qw = g_qf + blockIdx.x * 4096;

    #pragma unroll
    for (int it = 0; it < 8; ++it){
        int idx = it*NT_ + tid;
        int r = idx >> 5, c4 = idx & 31;
        int gr = min(row0 + r, NU_-1);
        float4 v = *(const float4*)(ufea + (size_t)gr*D_ + c4*4);
        *(float4*)(pU + swz128(r, c4*4)) = v;
    }
    const int tx = tid & 15, ty = tid >> 4;
    #pragma unroll 1
    for (int h = 0; h < 4; ++h){
        __syncthreads();
        #pragma unroll
        for (int it = 0; it < 4; ++it){
            int idx = it*NT_ + tid;
            int lr = idx >> 5, c4 = idx & 31;
            float4 w = *(const float4*)(W + (size_t)(h*32+lr)*D_ + c4*4);
            *(float4*)(pW + swz128(lr, c4*4)) = w;
        }
        __syncthreads();
        float acc[4][2] = {};
        #pragma unroll
        for (int k4 = 0; k4 < 32; ++k4){
            float4 wv[2];
            #pragma unroll
            for (int j = 0; j < 2; ++j)
                wv[j] = *(const float4*)(pW + swz128(tx*2+j, k4*4));
            #pragma unroll
            for (int i = 0; i < 4; ++i){
                float4 uv = *(const float4*)(pU + swz128(ty*4+i, k4*4));
                #pragma unroll
                for (int j = 0; j < 2; ++j){
                    acc[i][j] += uv.x*wv[j].x; acc[i][j] += uv.y*wv[j].y;
                    acc[i][j] += uv.z*wv[j].z; acc[i][j] += uv.w*wv[j].w;
                }
            }
        }
        const int c = h*32 + tx*2;
        const int ks = c >> 4, dd = c & 15;
        const int regb = (dd < 8) ? 0 : 2;
        const int tq = (dd & 7) >> 1;
        #pragma unroll
        for (int i = 0; i < 4; ++i){
            int r = ty*4 + i;
            int wmq = r >> 4, rw = r & 15, gq = rw & 7, hi = rw >> 3;
            uint32_t pk = h2u(acc[i][0] + bias[c], acc[i][1] + bias[c+1]);
            qw[(((wmq*8 + ks)*32) + gq*4 + tq)*4 + regb + hi] = pk;
        }
    }
}

// ================= main: persistent CTAs, dynamic units =================
__global__ __launch_bounds__(NT_, 2)
void gat_main(const float* __restrict__ inter, const int* __restrict__ adj)
{
    extern __shared__ char smc[];
    float* sL = (float*)(smc + B_L);
    int*   sU = (int*)(smc + B_U);
    const uint32_t smb = smem_u32(smc);

    const int tid  = threadIdx.x;
    const int lane = tid & 31, warp = tid >> 5;
    const int g    = lane >> 2, tig = lane & 3;
    const int wm   = warp >> 1, wn  = warp & 1;

    const int m0 = wm*16, n0 = wn*32, nd0 = wn*64;
    const int laneM = lane & 7;
    const int jloS = ((lane>>4)&1) << 3, chS = (lane>>3)&1;
    const int jloO = ((lane>>3)&1) << 3, chO = (lane>>4)&1;
    const int jS0 = n0 + jloS + laneM,  jS1 = jS0 + 16;
    const uint32_t rbS0 = (uint32_t)(jS0*256), rbS1 = (uint32_t)(jS1*256);
    const int j7S0 = jS0 & 7, j7S1 = jS1 & 7;

    for (;;){
        if (tid == 0) sU[0] = atomicAdd(&g_unit, 1);
        __syncthreads();                     // also fences prev unit's smem use
        const int u = sU[0];
        if (u >= UNITS_) break;
        const int spl = u / NRB_, rb = u - spl*NRB_;
        const int row0 = rb*BM_, item0 = spl*IPS_;

        // ---- load Q A-frags ----
        {
            const uint4* src = (const uint4*)g_qf + rb*1024;
            #pragma unroll
            for (int k = 0; k < 4; ++k)
                *(uint4*)(smc + B_SQ + ((k*256 + tid)<<4)) = src[k*256 + tid];
        }
        // ---- I(0) -> buf0 ----
        #pragma unroll
        for (int p = 0; p < 4; ++p){
            int j0 = (p*8 + warp)*2;
            int gm0 = min(item0 + j0,     NI_-1);
            int gm1 = min(item0 + j0 + 1, NI_-1);
            float4 v0 = *(const float4*)(inter + (size_t)gm0*D_ + lane*4);
            float4 v1 = *(const float4*)(inter + (size_t)gm1*D_ + lane*4);
            STORE_I(B_I0, j0,   v0);
            STORE_I(B_I0, j0+1, v1);
        }
        __syncthreads();

        float oacc[8][4];
        #pragma unroll
        for (int i = 0; i < 8; ++i)
            #pragma unroll
            for (int j = 0; j < 4; ++j) oacc[i][j] = 0.f;
        float lacc0 = 0.f, lacc1 = 0.f;

        const int gr0 = min(row0 + m0 + g,     NU_-1);
        const int gr1 = min(row0 + m0 + 8 + g, NU_-1);
        const size_t arow0 = (size_t)gr0*NI_ + item0;
        const size_t arow1 = (size_t)gr1*NI_ + item0;

        #pragma unroll 1
        for (int t = 0; t < TILES_; ++t){
            const int cur = t & 1;
            const uint32_t ibase = smb + (cur ? B_I1 : B_I0);
            const int nbuf = cur ? B_I0 : B_I1;

            // ---- adj(t) prefetch (direct LDG int2) ----
            int2 a0[4], a1[4];
            #pragma unroll
            for (int nf = 0; nf < 4; ++nf){
                const int lc = t*64 + n0 + nf*8 + 2*tig;
                if (lc < IPS_){
                    a0[nf] = *(const int2*)(adj + arow0 + lc);
                    a1[nf] = *(const int2*)(adj + arow1 + lc);
                } else {
                    a0[nf] = make_int2(0,0); a1[nf] = make_int2(0,0);
                }
            }

            // ---- I(t+1) prefetch (first half) ----
            float4 pv0[4];
            if (t+1 < TILES_){
                #pragma unroll
                for (int p = 0; p < 2; ++p){
                    int j0 = (p*8 + warp)*2;
                    int gm0 = min(item0 + (t+1)*64 + j0,     NI_-1);
                    int gm1 = min(item0 + (t+1)*64 + j0 + 1, NI_-1);
                    pv0[p*2]   = *(const float4*)(inter + (size_t)gm0*D_ + lane*4);
                    pv0[p*2+1] = *(const float4*)(inter + (size_t)gm1*D_ + lane*4);
                }
            }

            // ---- S = Q . I^T ----
            float sacc[4][4];
            #pragma unroll
            for (int nf = 0; nf < 4; ++nf)
                #pragma unroll
                for (int j = 0; j < 4; ++j) sacc[nf][j] = 0.f;
            #pragma unroll
            for (int ks = 0; ks < 8; ++ks){
                uint4 a4 = *(const uint4*)(smc + B_SQ + (((wm*8+ks)*32 + lane)<<4));
                const uint32_t A[4] = { a4.x, a4.y, a4.z, a4.w };
                uint32_t r[4];
                ldsm4(r, ibase + rbS0 + (uint32_t)((((2*ks + chS) ^ j7S0))<<4));
                mma16(sacc[0], A, r);
                mma16(sacc[1], A, r+2);
                ldsm4(r, ibase + rbS1 + (uint32_t)((((2*ks + chS) ^ j7S1))<<4));
                mma16(sacc[2], A, r);
                mma16(sacc[3], A, r+2);
            }

            // ---- store I(t+1) first half (other buffer; safe since sync(t-1)) ----
            if (t+1 < TILES_){
                const int j0 = warp*2, j1 = 16 + warp*2;
                STORE_I(nbuf, j0,   pv0[0]);
                STORE_I(nbuf, j0+1, pv0[1]);
                STORE_I(nbuf, j1,   pv0[2]);
                STORE_I(nbuf, j1+1, pv0[3]);
            }
            // ---- I(t+1) prefetch (second half) ----
            float4 pv1[4];
            if (t+1 < TILES_){
                #pragma unroll
                for (int p = 2; p < 4; ++p){
                    int j0 = (p*8 + warp)*2;
                    int gm0 = min(item0 + (t+1)*64 + j0,     NI_-1);
                    int gm1 = min(item0 + (t+1)*64 + j0 + 1, NI_-1);
                    pv1[(p-2)*2]   = *(const float4*)(inter + (size_t)gm0*D_ + lane*4);
                    pv1[(p-2)*2+1] = *(const float4*)(inter + (size_t)gm1*D_ + lane*4);
                }
            }

            // ---- epilogue: scale, leaky2, mask, exp; P -> fp16 A-frags ----
            #pragma unroll
            for (int nf = 0; nf < 4; ++nf){
                float v00 = sacc[nf][0]*SCALE_; v00 = fminf(v00, 2.f*v00);
                float v01 = sacc[nf][1]*SCALE_; v01 = fminf(v01, 2.f*v01);
                float v10 = sacc[nf][2]*SCALE_; v10 = fminf(v10, 2.f*v10);
                float v11 = sacc[nf][3]*SCALE_; v11 = fminf(v11, 2.f*v11);
                float p00 = (a0[nf].x > 0) ? __expf(v00) : 0.f;
                float p01 = (a0[nf].y > 0) ? __expf(v01) : 0.f;
                float p10 = (a1[nf].x > 0) ? __expf(v10) : 0.f;
                float p11 = (a1[nf].y > 0) ? __expf(v11) : 0.f;
                lacc0 += p00 + p01;
                lacc1 += p10 + p11;
                sacc[nf][0] = p00; sacc[nf][1] = p01;
                sacc[nf][2] = p10; sacc[nf][3] = p11;
            }
            #pragma unroll
            for (int kl = 0; kl < 2; ++kl){
                uint4 pk;
                pk.x = h2u(sacc[2*kl][0],   sacc[2*kl][1]);
                pk.y = h2u(sacc[2*kl][2],   sacc[2*kl][3]);
                pk.z = h2u(sacc[2*kl+1][0], sacc[2*kl+1][1]);
                pk.w = h2u(sacc[2*kl+1][2], sacc[2*kl+1][3]);
                *(uint4*)(smc + B_SP + (((wm*4 + wn*2 + kl)*32 + lane)<<4)) = pk;
            }
            BARW(1 + wm);                    // P visible within wm-pair

            // ---- O += P . I ----
            #pragma unroll
            for (int kso = 0; kso < 4; ++kso){
                uint4 a4 = *(const uint4*)(smc + B_SP + (((wm*4+kso)*32 + lane)<<4));
                const uint32_t A[4] = { a4.x, a4.y, a4.z, a4.w };
                const int j = kso*16 + jloO + laneM;
                const uint32_t rbb = ibase + (uint32_t)(j*256);
                const int j7 = j & 7;
                #pragma unroll
                for (int nh = 0; nh < 4; ++nh){
                    uint32_t r[4];
                    ldsm4t(r, rbb + (uint32_t)(((((nd0>>3) + nh*2 + chO) ^ j7))<<4));
                    mma16(oacc[nh*2],   A, r);
                    mma16(oacc[nh*2+1], A, r+2);
                }
            }

            // ---- store I(t+1) second half ----
            if (t+1 < TILES_){
                const int j2 = 32 + warp*2, j3 = 48 + warp*2;
                STORE_I(nbuf, j2,   pv1[0]);
                STORE_I(nbuf, j2+1, pv1[1]);
                STORE_I(nbuf, j3,   pv1[2]);
                STORE_I(nbuf, j3+1, pv1[3]);
            }
            __syncthreads();
        }

        // ---- l reduction ----
        lacc0 += __shfl_xor_sync(0xffffffffu, lacc0, 1);
        lacc0 += __shfl_xor_sync(0xffffffffu, lacc0, 2);
        lacc1 += __shfl_xor_sync(0xffffffffu, lacc1, 1);
        lacc1 += __shfl_xor_sync(0xffffffffu, lacc1, 2);
        if (tig == 0){
            sL[wn*64 + m0 + g]     = lacc0;
            sL[wn*64 + m0 + 8 + g] = lacc1;
        }
        __syncthreads();
        if (tid < BM_) g_lp[spl][row0 + tid] = sL[tid] + sL[64 + tid];

        // ---- write unnormalized partial O ----
        {
            const int r0g = row0 + m0 + g, r1g = row0 + m0 + 8 + g;
            #pragma unroll
            for (int nf = 0; nf < 8; ++nf){
                const int dd = nd0 + nf*8 + 2*tig;
                if (r0g < NU_)
                    *(float2*)(&g_op[spl][(size_t)r0g*D_ + dd]) =
                        make_float2(oacc[nf][0], oacc[nf][1]);
                if (r1g < NU_)
                    *(float2*)(&g_op[spl][(size_t)r1g*D_ + dd]) =
                        make_float2(oacc[nf][2], oacc[nf][3]);
            }
        }
    }
}

// ================= combine splits & normalize =================
__global__ __launch_bounds__(256) void gat_reduce(float* __restrict__ out)
{
    int idx = blockIdx.x*256 + threadIdx.x;
    int rr = idx >> 5, c4 = idx & 31;
    if (rr >= NU_) return;
    float l = 0.f;
    #pragma unroll
    for (int s = 0; s < NSPL_; ++s) l += g_lp[s][rr];
    float4 acc = make_float4(0.f, 0.f, 0.f, 0.f);
    #pragma unroll
    for (int s = 0; s < NSPL_; ++s){
        float4 a = *(const float4*)(&g_op[s][(size_t)rr*D_ + c4*4]);
        acc.x += a.x; acc.y += a.y; acc.z += a.z; acc.w += a.w;
    }
    float inv = 1.0f / l;
    float4 o = make_float4(acc.x*inv, acc.y*inv, acc.z*inv, acc.w*inv);
    *(float4*)(out + (size_t)rr*D_ + c4*4) = o;
}

extern "C" void kernel_launch(void* const* d_in, const int* in_sizes, int n_in,
                              void* d_out, int out_size)
{
    const float* ufea  = (const float*)d_in[0];
    const float* inter = (const float*)d_in[1];
    const int*   adj   = (const int*)  d_in[2];
    const float* W     = (const float*)d_in[3];
    const float* bias  = (const float*)d_in[4];
    for (int i = 0; i < n_in; ++i) {
        int s = in_sizes[i];
        if      (s == NU_*D_)  ufea  = (const float*)d_in[i];
        else if (s == NI_*D_)  inter = (const float*)d_in[i];
        else if (s == NU_*NI_) adj   = (const int*)d_in[i];
        else if (s == D_*D_)   W     = (const float*)d_in[i];
        else if (s == D_)      bias  = (const float*)d_in[i];
    }

    cudaFuncSetAttribute(gat_qk,   cudaFuncAttributeMaxDynamicSharedMemorySize, 49152);
    cudaFuncSetAttribute(gat_main, cudaFuncAttributeMaxDynamicSharedMemorySize, SMEM_B);

    gat_init<<<1, 1>>>();
    gat_qk<<<NRB_, NT_, 49152>>>(ufea, W, bias);
    gat_main<<<GRID_, NT_, SMEM_B>>>(inter, adj);
    gat_reduce<<<(NU_*32 + 255)/256, 256>>>((float*)d_out);
}

// round 15
// speedup vs baseline: 1.5910x; 1.4088x over previous
#include <cuda_runtime.h>
#include <cuda_fp16.h>
#include <cstdint>

// GAT forward_user: fp16 mma.sync, persistent CTAs + dynamic queue,
// pre-converted fp16 inter (ldmatrix swizzle baked into gmem) + cp.async.
// FIX vs R13: item0 must be 64-aligned (the baked swizzle uses gm&7 == local
// j&7 only then). IPS_=768; last split handles the 480-item remainder with a
// dynamic tile count and adj masking.
//   gat_ih:   inter -> g_ih fp16, smem-tile byte layout
//   gat_qk:   Q = ufea@W^T+b (fp32 exact) -> fp16 A-fragments in gmem
//   gat_main: units = (row-block 64) x (item-split of 16, 768 items);
//             per 64-item tile: S=Q.I^T; P=exp(mask(leaky2(S/sqrt(D))));
//             l+=rowsum; O+=P.I   [exp(-9e15)=0 => no max pass]
//   gat_reduce: out = (sum_s O_s)/(sum_s l_s)

#define D_     128
#define NU_    10000
#define NI_    12000
#define BM_    64
#define NRB_   157
#define NRPAD_ (NRB_*BM_)
#define NSPL_  16
#define IPS_   768           // 64-aligned; split 15 covers 480 items
#define TILES_ 12
#define UNITS_ (NRB_*NSPL_)  // 2512
#define GRID_  296
#define NT_    256
#define SCALE_ 0.08838834764831843f

__device__ float    g_op[NSPL_][(size_t)NRPAD_*D_];
__device__ float    g_lp[NSPL_][NRPAD_];
__device__ uint32_t g_qf[NRB_*4096];     // Q A-frags, 16KB per row-block
__device__ uint4    g_ih[NI_*16];        // inter fp16, tile-layout swizzled
__device__ int      g_unit;

// ---- helpers ----
__device__ __forceinline__ uint32_t h2u(float a, float b){
    __half2 h = __floats2half2_rn(a, b);
    return *(uint32_t*)&h;
}
__device__ __forceinline__ void mma16(float* d, const uint32_t* a, const uint32_t* b){
    asm volatile("mma.sync.aligned.m16n8k16.row.col.f32.f16.f16.f32 "
        "{%0,%1,%2,%3}, {%4,%5,%6,%7}, {%8,%9}, {%0,%1,%2,%3};"
        : "+f"(d[0]), "+f"(d[1]), "+f"(d[2]), "+f"(d[3])
        : "r"(a[0]), "r"(a[1]), "r"(a[2]), "r"(a[3]), "r"(b[0]), "r"(b[1]));
}
__device__ __forceinline__ void ldsm4(uint32_t* r, uint32_t a){
    asm volatile("ldmatrix.sync.aligned.m8n8.x4.shared.b16 {%0,%1,%2,%3}, [%4];"
        : "=r"(r[0]), "=r"(r[1]), "=r"(r[2]), "=r"(r[3]) : "r"(a));
}
__device__ __forceinline__ void ldsm4t(uint32_t* r, uint32_t a){
    asm volatile("ldmatrix.sync.aligned.m8n8.x4.trans.shared.b16 {%0,%1,%2,%3}, [%4];"
        : "=r"(r[0]), "=r"(r[1]), "=r"(r[2]), "=r"(r[3]) : "r"(a));
}
__device__ __forceinline__ uint32_t smem_u32(const void* p){
    uint32_t a;
    asm("{ .reg .u64 t; cvta.to.shared.u64 t, %1; cvt.u32.u64 %0, t; }" : "=r"(a) : "l"(p));
    return a;
}
__device__ __forceinline__ void cpa16(uint32_t dst, const void* src){
    asm volatile("cp.async.cg.shared.global [%0], [%1], 16;" :: "r"(dst), "l"(src));
}
#define CP_COMMIT() asm volatile("cp.async.commit_group;" ::: "memory")
#define CP_WAIT0()  asm volatile("cp.async.wait_group 0;" ::: "memory")
#define BARW(id)    asm volatile("bar.sync %0, %1;" :: "r"(id), "r"(64) : "memory")

__device__ __forceinline__ int swz128(int r, int c){
    return (r<<7) | ((((c>>2) ^ (r&7)) << 2) | (c&3));
}

// smem byte offsets (gat_main)
#define B_SQ   0         // Q A-frag: [wm*8+ks][lane] uint4   16384
#define B_I0   16384     // I fp16 tile (double buffer)       16384
#define B_I1   32768     //                                   16384
#define B_SP   49152     // P A-frag                           8192
#define B_L    57344     // 128 floats                          512
#define B_U    57856     // unit broadcast                       16
#define SMEM_B 57984

// ================= init: reset work counter =================
__global__ void gat_init(){ g_unit = 0; }

// ================= inter -> fp16 swizzled tile layout =================
__global__ __launch_bounds__(256) void gat_ih(const float* __restrict__ inter)
{
    int gt = blockIdx.x*256 + threadIdx.x;       // over NI_*32
    int gm = gt >> 5, c4 = gt & 31;
    if (gm >= NI_) return;
    float4 v = *(const float4*)(inter + (size_t)gm*D_ + c4*4);
    // byte layout within 256B row == smem tile layout (valid since every
    // tile's item0 is 64-aligned => gm&7 == local row&7):
    int slot = (((c4>>1) ^ (gm&7)) << 1) | (c4 & 1);
    ((uint2*)g_ih)[gm*32 + slot] = make_uint2(h2u(v.x, v.y), h2u(v.z, v.w));
}

// ================= Q kernel: fp32-exact, store fp16 A-frags =================
__global__ __launch_bounds__(NT_, 1)
void gat_qk(const float* __restrict__ ufea, const float* __restrict__ W,
            const float* __restrict__ bias)
{
    extern __shared__ char smc[];
    float* pU = (float*)smc;                 // 32KB
    float* pW = (float*)(smc + 32768);       // 16KB
    const int tid = threadIdx.x;
    const int row0 = blockIdx.x * BM_;
    uint32_t* qw = g_qf + blockIdx.x * 4096;

    #pragma unroll
    for (int it = 0; it < 8; ++it){
        int idx = it*NT_ + tid;
        int r = idx >> 5, c4 = idx & 31;
        int gr = min(row0 + r, NU_-1);
        float4 v = *(const float4*)(ufea + (size_t)gr*D_ + c4*4);
        *(float4*)(pU + swz128(r, c4*4)) = v;
    }
    const int tx = tid & 15, ty = tid >> 4;
    #pragma unroll 1
    for (int h = 0; h < 4; ++h){
        __syncthreads();
        #pragma unroll
        for (int it = 0; it < 4; ++it){
            int idx = it*NT_ + tid;
            int lr = idx >> 5, c4 = idx & 31;
            float4 w = *(const float4*)(W + (size_t)(h*32+lr)*D_ + c4*4);
            *(float4*)(pW + swz128(lr, c4*4)) = w;
        }
        __syncthreads();
        float acc[4][2] = {};
        #pragma unroll
        for (int k4 = 0; k4 < 32; ++k4){
            float4 wv[2];
            #pragma unroll
            for (int j = 0; j < 2; ++j)
                wv[j] = *(const float4*)(pW + swz128(tx*2+j, k4*4));
            #pragma unroll
            for (int i = 0; i < 4; ++i){
                float4 uv = *(const float4*)(pU + swz128(ty*4+i, k4*4));
                #pragma unroll
                for (int j = 0; j < 2; ++j){
                    acc[i][j] += uv.x*wv[j].x; acc[i][j] += uv.y*wv[j].y;
                    acc[i][j] += uv.z*wv[j].z; acc[i][j] += uv.w*wv[j].w;
                }
            }
        }
        const int c = h*32 + tx*2;
        const int ks = c >> 4, dd = c & 15;
        const int regb = (dd < 8) ? 0 : 2;
        const int tq = (dd & 7) >> 1;
        #pragma unroll
        for (int i = 0; i < 4; ++i){
            int r = ty*4 + i;
            int wmq = r >> 4, rw = r & 15, gq = rw & 7, hi = rw >> 3;
            uint32_t pk = h2u(acc[i][0] + bias[c], acc[i][1] + bias[c+1]);
            qw[(((wmq*8 + ks)*32) + gq*4 + tq)*4 + regb + hi] = pk;
        }
    }
}

// ================= main: persistent CTAs, dynamic units =================
__global__ __launch_bounds__(NT_, 2)
void gat_main(const int* __restrict__ adj)
{
    extern __shared__ char smc[];
    float* sL = (float*)(smc + B_L);
    int*   sU = (int*)(smc + B_U);
    const uint32_t smb = smem_u32(smc);

    const int tid  = threadIdx.x;
    const int lane = tid & 31, warp = tid >> 5;
    const int g    = lane >> 2, tig = lane & 3;
    const int wm   = warp >> 1, wn  = warp & 1;

    const int m0 = wm*16, n0 = wn*32, nd0 = wn*64;
    const int laneM = lane & 7;
    const int jloS = ((lane>>4)&1) << 3, chS = (lane>>3)&1;
    const int jloO = ((lane>>3)&1) << 3, chO = (lane>>4)&1;
    const int jS0 = n0 + jloS + laneM,  jS1 = jS0 + 16;
    const uint32_t rbS0 = (uint32_t)(jS0*256), rbS1 = (uint32_t)(jS1*256);
    const int j7S0 = jS0 & 7, j7S1 = jS1 & 7;
    // cp.async per-thread chunk mapping
    const int cpj = tid >> 4, cpc = (tid & 15) << 4;

    for (;;){
        if (tid == 0) sU[0] = atomicAdd(&g_unit, 1);
        __syncthreads();                     // also fences prev unit's smem use
        const int u = sU[0];
        if (u >= UNITS_) break;
        const int spl = u / NRB_, rb = u - spl*NRB_;
        const int row0 = rb*BM_, item0 = spl*IPS_;
        const int valid = min(IPS_, NI_ - item0);   // 768, or 480 for spl=15
        const int nt = (valid + 63) >> 6;           // 12 or 8 tiles

        // ---- issue I(0) -> buf0 (cp.async 16B, swizzle baked in g_ih) ----
        #pragma unroll
        for (int it = 0; it < 4; ++it){
            int j = it*16 + cpj;
            int gm = min(item0 + j, NI_-1);
            cpa16(smb + B_I0 + (uint32_t)(j*256 + cpc),
                  (const char*)g_ih + (size_t)gm*256 + cpc);
        }
        CP_COMMIT();

        // ---- load Q A-frags ----
        {
            const uint4* src = (const uint4*)g_qf + rb*1024;
            #pragma unroll
            for (int k = 0; k < 4; ++k)
                *(uint4*)(smc + B_SQ + ((k*256 + tid)<<4)) = src[k*256 + tid];
        }

        float oacc[8][4];
        #pragma unroll
        for (int i = 0; i < 8; ++i)
            #pragma unroll
            for (int j = 0; j < 4; ++j) oacc[i][j] = 0.f;
        float lacc0 = 0.f, lacc1 = 0.f;

        const int gr0 = min(row0 + m0 + g,     NU_-1);
        const int gr1 = min(row0 + m0 + 8 + g, NU_-1);
        const size_t arow0 = (size_t)gr0*NI_ + item0;
        const size_t arow1 = (size_t)gr1*NI_ + item0;

        #pragma unroll 1
        for (int t = 0; t < nt; ++t){
            const uint32_t ibase = smb + ((t & 1) ? B_I1 : B_I0);
            const uint32_t nbase = smb + ((t & 1) ? B_I0 : B_I1);

            CP_WAIT0();                      // I(t) landed (thread-local)
            __syncthreads();                 // publish I(t); O(t-1) readers done

            // ---- issue I(t+1) into freed buffer ----
            if (t+1 < nt){
                #pragma unroll
                for (int it = 0; it < 4; ++it){
                    int j = it*16 + cpj;
                    int gm = min(item0 + (t+1)*64 + j, NI_-1);
                    cpa16(nbase + (uint32_t)(j*256 + cpc),
                          (const char*)g_ih + (size_t)gm*256 + cpc);
                }
                CP_COMMIT();
            }

            // ---- adj(t) prefetch (direct LDG int2) ----
            int2 a0[4], a1[4];
            #pragma unroll
            for (int nf = 0; nf < 4; ++nf){
                const int lc = t*64 + n0 + nf*8 + 2*tig;
                if (lc < valid){
                    a0[nf] = *(const int2*)(adj + arow0 + lc);
                    a1[nf] = *(const int2*)(adj + arow1 + lc);
                } else {
                    a0[nf] = make_int2(0,0); a1[nf] = make_int2(0,0);
                }
            }

            // ---- S = Q . I^T ----
            float sacc[4][4];
            #pragma unroll
            for (int nf = 0; nf < 4; ++nf)
                #pragma unroll
                for (int j = 0; j < 4; ++j) sacc[nf][j] = 0.f;
            #pragma unroll
            for (int ks = 0; ks < 8; ++ks){
                uint4 a4 = *(const uint4*)(smc + B_SQ + (((wm*8+ks)*32 + lane)<<4));
                const uint32_t A[4] = { a4.x, a4.y, a4.z, a4.w };
                uint32_t r[4];
                ldsm4(r, ibase + rbS0 + (uint32_t)((((2*ks + chS) ^ j7S0))<<4));
                mma16(sacc[0], A, r);
                mma16(sacc[1], A, r+2);
                ldsm4(r, ibase + rbS1 + (uint32_t)((((2*ks + chS) ^ j7S1))<<4));
                mma16(sacc[2], A, r);
                mma16(sacc[3], A, r+2);
            }

            // ---- epilogue: scale, leaky2, mask, exp; P -> fp16 A-frags ----
            #pragma unroll
            for (int nf = 0; nf < 4; ++nf){
                float v00 = sacc[nf][0]*SCALE_; v00 = fminf(v00, 2.f*v00);
                float v01 = sacc[nf][1]*SCALE_; v01 = fminf(v01, 2.f*v01);
                float v10 = sacc[nf][2]*SCALE_; v10 = fminf(v10, 2.f*v10);
                float v11 = sacc[nf][3]*SCALE_; v11 = fminf(v11, 2.f*v11);
                float p00 = (a0[nf].x > 0) ? __expf(v00) : 0.f;
                float p01 = (a0[nf].y > 0) ? __expf(v01) : 0.f;
                float p10 = (a1[nf].x > 0) ? __expf(v10) : 0.f;
                float p11 = (a1[nf].y > 0) ? __expf(v11) : 0.f;
                lacc0 += p00 + p01;
                lacc1 += p10 + p11;
                sacc[nf][0] = p00; sacc[nf][1] = p01;
                sacc[nf][2] = p10; sacc[nf][3] = p11;
            }
            #pragma unroll
            for (int kl = 0; kl < 2; ++kl){
                uint4 pk;
                pk.x = h2u(sacc[2*kl][0],   sacc[2*kl][1]);
                pk.y = h2u(sacc[2*kl][2],   sacc[2*kl][3]);
                pk.z = h2u(sacc[2*kl+1][0], sacc[2*kl+1][1]);
                pk.w = h2u(sacc[2*kl+1][2], sacc[2*kl+1][3]);
                *(uint4*)(smc + B_SP + (((wm*4 + wn*2 + kl)*32 + lane)<<4)) = pk;
            }
            BARW(1 + wm);                    // P visible within wm-pair

            // ---- O += P . I ----
            #pragma unroll
            for (int kso = 0; kso < 4; ++kso){
                uint4 a4 = *(const uint4*)(smc + B_SP + (((wm*4+kso)*32 + lane)<<4));
                const uint32_t A[4] = { a4.x, a4.y, a4.z, a4.w };
                const int j = kso*16 + jloO + laneM;
                const uint32_t rbb = ibase + (uint32_t)(j*256);
                const int j7 = j & 7;
                #pragma unroll
                for (int nh = 0; nh < 4; ++nh){
                    uint32_t r[4];
                    ldsm4t(r, rbb + (uint32_t)(((((nd0>>3) + nh*2 + chO) ^ j7))<<4));
                    mma16(oacc[nh*2],   A, r);
                    mma16(oacc[nh*2+1], A, r+2);
                }
            }
        }

        // ---- l reduction ----
        lacc0 += __shfl_xor_sync(0xffffffffu, lacc0, 1);
        lacc0 += __shfl_xor_sync(0xffffffffu, lacc0, 2);
        lacc1 += __shfl_xor_sync(0xffffffffu, lacc1, 1);
        lacc1 += __shfl_xor_sync(0xffffffffu, lacc1, 2);
        __syncthreads();                     // O-gemm done before sL reuse
        if (tig == 0){
            sL[wn*64 + m0 + g]     = lacc0;
            sL[wn*64 + m0 + 8 + g] = lacc1;
        }
        __syncthreads();
        if (tid < BM_) g_lp[spl][row0 + tid] = sL[tid] + sL[64 + tid];

        // ---- write unnormalized partial O ----
        {
            const int r0g = row0 + m0 + g, r1g = row0 + m0 + 8 + g;
            #pragma unroll
            for (int nf = 0; nf < 8; ++nf){
                const int dd = nd0 + nf*8 + 2*tig;
                if (r0g < NU_)
                    *(float2*)(&g_op[spl][(size_t)r0g*D_ + dd]) =
                        make_float2(oacc[nf][0], oacc[nf][1]);
                if (r1g < NU_)
                    *(float2*)(&g_op[spl][(size_t)r1g*D_ + dd]) =
                        make_float2(oacc[nf][2], oacc[nf][3]);
            }
        }
    }
}

// ================= combine splits & normalize =================
__global__ __launch_bounds__(256) void gat_reduce(float* __restrict__ out)
{
    int idx = blockIdx.x*256 + threadIdx.x;
    int rr = idx >> 5, c4 = idx & 31;
    if (rr >= NU_) return;
    float l = 0.f;
    #pragma unroll
    for (int s = 0; s < NSPL_; ++s) l += g_lp[s][rr];
    float4 acc = make_float4(0.f, 0.f, 0.f, 0.f);
    #pragma unroll
    for (int s = 0; s < NSPL_; ++s){
        float4 a = *(const float4*)(&g_op[s][(size_t)rr*D_ + c4*4]);
        acc.x += a.x; acc.y += a.y; acc.z += a.z; acc.w += a.w;
    }
    float inv = 1.0f / l;
    *(float4*)(out + (size_t)rr*D_ + c4*4) =
        make_float4(acc.x*inv, acc.y*inv, acc.z*inv, acc.w*inv);
}

extern "C" void kernel_launch(void* const* d_in, const int* in_sizes, int n_in,
                              void* d_out, int out_size)
{
    const float* ufea  = (const float*)d_in[0];
    const float* inter = (const float*)d_in[1];
    const int*   adj   = (const int*)  d_in[2];
    const float* W     = (const float*)d_in[3];
    const float* bias  = (const float*)d_in[4];
    for (int i = 0; i < n_in; ++i) {
        int s = in_sizes[i];
        if      (s == NU_*D_)  ufea  = (const float*)d_in[i];
        else if (s == NI_*D_)  inter = (const float*)d_in[i];
        else if (s == NU_*NI_) adj   = (const int*)d_in[i];
        else if (s == D_*D_)   W     = (const float*)d_in[i];
        else if (s == D_)      bias  = (const float*)d_in[i];
    }

    cudaFuncSetAttribute(gat_qk,   cudaFuncAttributeMaxDynamicSharedMemorySize, 49152);
    cudaFuncSetAttribute(gat_main, cudaFuncAttributeMaxDynamicSharedMemorySize, SMEM_B);

    gat_init<<<1, 1>>>();
    gat_ih<<<(NI_*32 + 255)/256, 256>>>(inter);
    gat_qk<<<NRB_, NT_, 49152>>>(ufea, W, bias);
    gat_main<<<GRID_, NT_, SMEM_B>>>(adj);
    gat_reduce<<<(NU_*32 + 255)/256, 256>>>((float*)d_out);
}